// round 15
// baseline (speedup 1.0000x reference)
#include <cuda_runtime.h>
#include <cuda_fp16.h>
#include <cstdint>
#include <cstddef>

// ---------------------------------------------------------------------------
// Problem constants
// ---------------------------------------------------------------------------
#define TOK   8192
#define DC    512
#define DM    2048
#define ASZ   ((size_t)TOK * DC)
#define WSZ   ((size_t)DC * DC)

// ---- shared smem layout -----------------------------------------------------
#define KB_OFF     65536
#define YB_OFF     131072
#define YSTR       1040
#define SCR_OFF    198656
#define MRS_OFF    202752
#define SMEM_K     204800

#define SWZ(x) ((x) ^ (((x) >> 3) & 0x70))

// ---------------------------------------------------------------------------
// Device scratch
// ---------------------------------------------------------------------------
#define W_PROJ 0
#define W_FUSE 4194304
#define W_UP   5242880
#define W_LAT  6291456
#define W_DOWN 7340032
#define W_OUT1 8126464
#define W_OUT2 8388608
__device__ __half g_wh[9437184];
__device__ __half g_cat [(size_t)TOK * DM];
__device__ __half g_x0  [TOK * DC];
__device__ __half g_acts[4 * TOK * DC];
__device__ __half g_h   [TOK * DC];

// ---------------------------------------------------------------------------
// PTX helpers
// ---------------------------------------------------------------------------
__device__ __forceinline__ uint32_t smem_u32(const void* p) {
    uint32_t a;
    asm("{ .reg .u64 t; cvta.to.shared.u64 t, %1; cvt.u32.u64 %0, t; }"
        : "=r"(a) : "l"(p));
    return a;
}
__device__ __forceinline__ void cp16(uint32_t d, const void* s) {
    asm volatile("cp.async.cg.shared.global [%0], [%1], 16;\n" :: "r"(d), "l"(s));
}
__device__ __forceinline__ void ldsm4(uint32_t& r0, uint32_t& r1,
                                      uint32_t& r2, uint32_t& r3, uint32_t a) {
    asm volatile("ldmatrix.sync.aligned.m8n8.x4.shared.b16 {%0,%1,%2,%3}, [%4];"
                 : "=r"(r0), "=r"(r1), "=r"(r2), "=r"(r3) : "r"(a));
}
__device__ __forceinline__ void mma16816(float* c, const uint32_t* a, const uint32_t* b) {
    asm volatile(
        "mma.sync.aligned.m16n8k16.row.col.f32.f16.f16.f32 "
        "{%0,%1,%2,%3}, {%4,%5,%6,%7}, {%8,%9}, {%0,%1,%2,%3};"
        : "+f"(c[0]), "+f"(c[1]), "+f"(c[2]), "+f"(c[3])
        : "r"(a[0]), "r"(a[1]), "r"(a[2]), "r"(a[3]), "r"(b[0]), "r"(b[1]));
}
#define CP_COMMIT() asm volatile("cp.async.commit_group;\n" ::: "memory")
#define CP_WAIT0()  asm volatile("cp.async.wait_group 0;\n" ::: "memory")
#define CP_WAIT1()  asm volatile("cp.async.wait_group 1;\n" ::: "memory")

enum { M_LN = 0, M_UPD_P = 1, M_UPD_NP = 2, M_GELU = 3, M_ADD = 4 };

// ---------------------------------------------------------------------------
// Merged weight fp32 -> fp16 convert
// ---------------------------------------------------------------------------
__global__ void wconv(const float2* p, const float2* f, const float2* u,
                      const float2* l, const float2* dw, const float2* o1,
                      const float2* o2, __half2* dst)
{
    const size_t N0 = 2097152, N1 = 524288, N2 = 524288, N3 = 524288,
                 N4 = 393216,  N5 = 131072, N6 = 524288;
    const size_t T = N0 + N1 + N2 + N3 + N4 + N5 + N6;
    size_t i = (size_t)blockIdx.x * blockDim.x + threadIdx.x;
    size_t st = (size_t)gridDim.x * blockDim.x;
    for (; i < T; i += st) {
        size_t j = i; const float2* s;
        if (j < N0) s = p + j;
        else { j -= N0; if (j < N1) s = f + j;
        else { j -= N1; if (j < N2) s = u + j;
        else { j -= N2; if (j < N3) s = l + j;
        else { j -= N3; if (j < N4) s = dw + j;
        else { j -= N4; if (j < N5) s = o1 + j;
        else { j -= N5; s = o2 + j; }}}}}}
        dst[i] = __float22half2_rn(*s);
    }
}

// ---------------------------------------------------------------------------
// k512 (R14 champion + shadowed interior loadA): CTA tile 64x512 two passes,
// warp tile 64x32, per-warp B double buffer, register stash, ybuf LN.
// ---------------------------------------------------------------------------
template<int MODE>
__global__ void __launch_bounds__(256, 1) k512(
    const __half* __restrict__ A1, const __half* __restrict__ A2,
    const __half* __restrict__ A3,
    const __half* __restrict__ W1, const __half* __restrict__ W2,
    const __half* __restrict__ W3,
    const float* __restrict__ b1, const float* __restrict__ b2,
    const float* __restrict__ b3,
    const float* __restrict__ lng, const float* __restrict__ lnb,
    const float* __restrict__ plog,
    const float* __restrict__ qwen, void* outv, int ldOut)
{
    extern __shared__ char sm[];
    const uint32_t smb = smem_u32(sm);
    const int tid = threadIdx.x, wid = tid >> 5, lane = tid & 31;
    const int g = lane >> 2, t = lane & 3;
    const size_t bm0 = (size_t)blockIdx.x * 64;
    const int colOff = blockIdx.y * 512;
    if (MODE == M_ADD) { W2 += (size_t)colOff * DC; b2 += colOff; }

    float acc[4][4][4];
    uint32_t stash[2][4][4][2];
    float rs[8], rq[8];
    float* part = (float*)(sm + SCR_OFF);
    float* mrs  = (float*)(sm + MRS_OFF);
    const uint32_t sBw = smb + KB_OFF + wid * 8192;

    auto loadA_issue = [&](const __half* Ap) {
#pragma unroll
        for (int i = 0; i < 16; i++) {
            int idx = tid + i * 256; int r = idx >> 6, c = idx & 63;
            cp16(smb + ((c >> 3) << 13) + SWZ(r * 128 + (c & 7) * 16),
                 Ap + (bm0 + (size_t)r) * DC + c * 8);
        }
        CP_COMMIT();
    };
    auto loadA = [&](const __half* Ap) {
        __syncthreads();
        loadA_issue(Ap);
        CP_WAIT0(); __syncthreads();
    };

    auto run_gemm = [&](const __half* W, int pass) {
#pragma unroll
        for (int mi = 0; mi < 4; mi++)
#pragma unroll
            for (int ni = 0; ni < 4; ni++)
#pragma unroll
                for (int q = 0; q < 4; q++) acc[mi][ni][q] = 0.f;
        const __half* Wp = W + (size_t)(pass * 256 + wid * 32) * DC;
        auto loadBw = [&](int buf, int kt) {
            const uint32_t sB = sBw + buf * 4096;
            const int k0 = kt * 64;
#pragma unroll
            for (int i = 0; i < 8; i++) {
                int idx = lane + i * 32; int r = idx >> 3, ch = idx & 7;
                cp16(sB + SWZ(r * 128 + ch * 16),
                     Wp + (size_t)r * DC + k0 + ch * 8);
            }
            CP_COMMIT();
        };
        loadBw(0, 0);
        loadBw(1, 1);
        uint32_t a[2][4][4], b[2][2][4];
        auto ldsmA = [&](int buf, int ks, uint32_t sA) {
#pragma unroll
            for (int mi = 0; mi < 4; mi++) {
                int m  = mi * 16 + (lane & 7) + ((lane >> 3) & 1) * 8;
                int kb = ks * 32 + (lane >> 4) * 16;
                ldsm4(a[buf][mi][0], a[buf][mi][1], a[buf][mi][2], a[buf][mi][3],
                      sA + SWZ(m * 128 + kb));
            }
        };
        auto ldsmB = [&](int buf, int ks, uint32_t sB) {
#pragma unroll
            for (int p = 0; p < 2; p++) {
                int n  = p * 16 + (lane >> 4) * 8 + (lane & 7);
                int kb = ks * 32 + ((lane >> 3) & 1) * 16;
                ldsm4(b[buf][p][0], b[buf][p][1], b[buf][p][2], b[buf][p][3],
                      sB + SWZ(n * 128 + kb));
            }
        };
#pragma unroll 1
        for (int kt = 0; kt < 8; kt++) {
            if (kt == 7) { CP_WAIT0(); } else { CP_WAIT1(); }
            const uint32_t sA = smb + kt * 8192;
            const uint32_t sB = sBw + (kt & 1) * 4096;
            if (kt == 0) ldsmA(0, 0, sA);
            ldsmB(0, 0, sB);
#pragma unroll
            for (int ks = 0; ks < 4; ks++) {
                const int cur = ks & 1;
                if (ks < 3) { ldsmA(cur ^ 1, ks + 1, sA); ldsmB(cur ^ 1, ks + 1, sB); }
                else if (kt < 7) ldsmA(cur ^ 1, 0, smb + (kt + 1) * 8192);
#pragma unroll
                for (int mi = 0; mi < 4; mi++)
#pragma unroll
                    for (int p = 0; p < 2; p++) {
                        mma16816(acc[mi][2 * p],     a[cur][mi], &b[cur][p][0]);
                        mma16816(acc[mi][2 * p + 1], a[cur][mi], &b[cur][p][2]);
                    }
            }
            if (kt < 6) loadBw(kt & 1, kt + 2);
        }
    };

    auto zero_stats = [&]() {
#pragma unroll
        for (int i = 0; i < 8; i++) { rs[i] = 0.f; rq[i] = 0.f; }
    };
    auto ln_stats = [&]() {
#pragma unroll
        for (int r8 = 0; r8 < 8; r8++) {
            float s = rs[r8], q = rq[r8];
            s += __shfl_xor_sync(0xffffffffu, s, 1); q += __shfl_xor_sync(0xffffffffu, q, 1);
            s += __shfl_xor_sync(0xffffffffu, s, 2); q += __shfl_xor_sync(0xffffffffu, q, 2);
            if (t == 0) {
                const int row = (r8 >> 1) * 16 + g + (r8 & 1) * 8;
                part[row * 16 + wid * 2]     = s;
                part[row * 16 + wid * 2 + 1] = q;
            }
        }
        __syncthreads();
        if (tid < 64) {
            float s = 0.f, q = 0.f;
#pragma unroll
            for (int w = 0; w < 8; w++) { s += part[tid * 16 + w * 2]; q += part[tid * 16 + w * 2 + 1]; }
            const float mean = s * (1.f / 512.f);
            const float var  = q * (1.f / 512.f) - mean * mean;
            mrs[tid * 2]     = mean;
            mrs[tid * 2 + 1] = rsqrtf(var + 1e-5f);
        }
        __syncthreads();
    };

    __half* outH = (__half*)outv;
    float*  outF = (float*)outv;

    auto flatnorm = [&](__half* outg) {
        const float2 lgv = *(const float2*)(lng + tid * 2);
        const float2 lbv = *(const float2*)(lnb + tid * 2);
#pragma unroll 4
        for (int row = 0; row < 64; row++) {
            __half2 hv = *(__half2*)(sm + YB_OFF + row * YSTR + tid * 4);
            float2 f = __half22float2(hv);
            const float mean = mrs[row * 2], rstd = mrs[row * 2 + 1];
            *(__half2*)(outg + (bm0 + row) * DC + 2 * tid) =
                __floats2half2_rn((f.x - mean) * rstd * lgv.x + lbv.x,
                                  (f.y - mean) * rstd * lgv.y + lbv.y);
        }
    };

    // ---------------- phase 1: pred (UPD_P only) ------------------------------
    if (MODE == M_UPD_P) {
        loadA(A1);
#pragma unroll 1
        for (int pass = 0; pass < 2; pass++) {
            run_gemm(W1, pass);
            if (pass == 1) { __syncthreads(); loadA_issue(A2); }  // shadow A2
#pragma unroll
            for (int ni = 0; ni < 4; ni++) {
                const int c = pass * 256 + wid * 32 + ni * 8 + 2 * t;
                const float2 bp = *(const float2*)(b1 + c);
#pragma unroll
                for (int mi = 0; mi < 4; mi++)
#pragma unroll
                    for (int h = 0; h < 2; h++) {
                        __half2 hv = __floats2half2_rn(acc[mi][ni][2 * h] + bp.x,
                                                       acc[mi][ni][2 * h + 1] + bp.y);
                        stash[pass][mi][ni][h] = *(uint32_t*)&hv;
                    }
            }
        }
        CP_WAIT0(); __syncthreads();
    } else if (MODE == M_LN || MODE == M_UPD_NP || MODE == M_GELU || MODE == M_ADD) {
        loadA(A2);
    }

    // ---------------- phase 2: main / comp GEMM -------------------------------
    if (MODE == M_LN || MODE == M_UPD_P || MODE == M_UPD_NP) {
        zero_stats();
#pragma unroll 1
        for (int pass = 0; pass < 2; pass++) {
            run_gemm(W2, pass);
#pragma unroll
            for (int ni = 0; ni < 4; ni++) {
                const int c = pass * 256 + wid * 32 + ni * 8 + 2 * t;
                const float2 bp = *(const float2*)(b2 + c);
                const uint32_t ya = smb + YB_OFF + (uint32_t)(c >> 1) * 4;
#pragma unroll
                for (int mi = 0; mi < 4; mi++)
#pragma unroll
                    for (int h = 0; h < 2; h++) {
                        const int row = mi * 16 + g + h * 8;
                        float vx = acc[mi][ni][2 * h]     + bp.x;
                        float vy = acc[mi][ni][2 * h + 1] + bp.y;
                        rs[mi * 2 + h] += vx + vy;
                        rq[mi * 2 + h] += vx * vx + vy * vy;
                        __half2 hv = __floats2half2_rn(vx, vy);
                        *(__half2*)(sm + (ya - smb) + (uint32_t)row * YSTR) = hv;
                    }
            }
        }
        ln_stats();
        if (MODE == M_LN) {
            flatnorm(outH);
        } else {
            loadA_issue(A3);                 // shadow A3 behind normalize-stash
#pragma unroll
            for (int pass = 0; pass < 2; pass++)
#pragma unroll
                for (int ni = 0; ni < 4; ni++) {
                    const int c = pass * 256 + wid * 32 + ni * 8 + 2 * t;
                    const float2 lgc = *(const float2*)(lng + c);
                    const float2 lbc = *(const float2*)(lnb + c);
#pragma unroll
                    for (int mi = 0; mi < 4; mi++)
#pragma unroll
                        for (int h = 0; h < 2; h++) {
                            const int row = mi * 16 + g + h * 8;
                            const float mean = mrs[row * 2], rstd = mrs[row * 2 + 1];
                            __half2 hv = *(__half2*)(sm + YB_OFF + row * YSTR + (c >> 1) * 4);
                            float2 f = __half22float2(hv);
                            const float cx = (f.x - mean) * rstd * lgc.x + lbc.x;
                            const float cy = (f.y - mean) * rstd * lgc.y + lbc.y;
                            __half2 sv;
                            if (MODE == M_UPD_P) {
                                float2 pf = __half22float2(*(__half2*)&stash[pass][mi][ni][h]);
                                sv = __floats2half2_rn(cx - pf.x, cy - pf.y);
                            } else {
                                sv = __floats2half2_rn(cx, cy);
                            }
                            stash[pass][mi][ni][h] = *(uint32_t*)&sv;
                        }
                }
            CP_WAIT0(); __syncthreads();
        }
    } else {
#pragma unroll 1
        for (int pass = 0; pass < 2; pass++) {
            run_gemm(W2, pass);
#pragma unroll
            for (int ni = 0; ni < 4; ni++) {
                const int c = pass * 256 + wid * 32 + ni * 8 + 2 * t;
                const float2 bp = *(const float2*)(b2 + c);
#pragma unroll
                for (int mi = 0; mi < 4; mi++)
#pragma unroll
                    for (int h = 0; h < 2; h++) {
                        const int row = mi * 16 + g + h * 8;
                        float vx = acc[mi][ni][2 * h]     + bp.x;
                        float vy = acc[mi][ni][2 * h + 1] + bp.y;
                        if (MODE == M_GELU) {
                            vx = 0.5f * vx * (1.f + erff(vx * 0.70710678118f));
                            vy = 0.5f * vy * (1.f + erff(vy * 0.70710678118f));
                            *(__half2*)(outH + (bm0 + row) * (size_t)ldOut + c) =
                                __floats2half2_rn(vx, vy);
                        } else {
                            const float2 qv = *(const float2*)
                                (qwen + (bm0 + row) * (size_t)DM + colOff + c);
                            float2 o; o.x = vx + qv.x; o.y = vy + qv.y;
                            *(float2*)(outF + (bm0 + row) * (size_t)ldOut + colOff + c) = o;
                        }
                    }
            }
        }
    }

    // ---------------- phase 3: lateral GEMM + update + LN ---------------------
    if (MODE == M_UPD_P || MODE == M_UPD_NP) {
        zero_stats();
#pragma unroll 1
        for (int pass = 0; pass < 2; pass++) {
            run_gemm(W3, pass);
#pragma unroll
            for (int ni = 0; ni < 4; ni++) {
                const int c = pass * 256 + wid * 32 + ni * 8 + 2 * t;
                const float2 bp = *(const float2*)(b3 + c);
                const float px = 1.f / (1.f + __expf(-plog[c]));
                const float py = 1.f / (1.f + __expf(-plog[c + 1]));
                const uint32_t cblk = ((uint32_t)(c >> 6) << 13);
                const uint32_t cin  = (uint32_t)(c & 63) * 2;
#pragma unroll
                for (int mi = 0; mi < 4; mi++)
#pragma unroll
                    for (int h = 0; h < 2; h++) {
                        const int row = mi * 16 + g + h * 8;
                        __half2 ah = *(__half2*)(sm + cblk + SWZ((uint32_t)row * 128 + cin));
                        float2 af = __half22float2(ah);
                        float2 sf = __half22float2(*(__half2*)&stash[pass][mi][ni][h]);
                        float dx, dy;
                        if (MODE == M_UPD_P) { dx = sf.x; dy = sf.y; }
                        else                 { dx = sf.x - af.x; dy = sf.y - af.y; }
                        const float yx =
                            af.x + 0.5f * px * dx + 0.1f * (acc[mi][ni][2 * h] + bp.x);
                        const float yy =
                            af.y + 0.5f * py * dy + 0.1f * (acc[mi][ni][2 * h + 1] + bp.y);
                        rs[mi * 2 + h] += yx + yy;
                        rq[mi * 2 + h] += yx * yx + yy * yy;
                        *(__half2*)(sm + YB_OFF + (uint32_t)row * YSTR + (uint32_t)(c >> 1) * 4) =
                            __floats2half2_rn(yx, yy);
                    }
            }
        }
        ln_stats();
        flatnorm(outH);
    }
}

// ---------------------------------------------------------------------------
// kfuse0: fused INIT sweep (verified R14 kernel, unchanged).
// ---------------------------------------------------------------------------
__global__ void __launch_bounds__(256, 1) kfuse0(
    const __half* __restrict__ x0g, __half* acts,
    const __half* __restrict__ wh, const float* __restrict__ up_b,
    const float* __restrict__ lng_all, const float* __restrict__ lnb_all)
{
    extern __shared__ char sm[];
    const uint32_t smb = smem_u32(sm);
    const int tid = threadIdx.x, wid = tid >> 5, lane = tid & 31;
    const int g = lane >> 2, t = lane & 3;
    const size_t bm0 = (size_t)blockIdx.x * 64;

    float acc[4][4][4];
    float rs[8], rq[8];
    float* part = (float*)(sm + SCR_OFF);
    float* mrs  = (float*)(sm + MRS_OFF);
    const uint32_t sBw = smb + KB_OFF + wid * 8192;
    bool carried = false;

    auto loadBw_at = [&](const __half* Wp, int buf, int kt) {
        const uint32_t sB = sBw + buf * 4096;
        const int k0 = kt * 64;
#pragma unroll
        for (int i = 0; i < 8; i++) {
            int idx = lane + i * 32; int r = idx >> 3, ch = idx & 7;
            cp16(sB + SWZ(r * 128 + ch * 16),
                 Wp + (size_t)r * DC + k0 + ch * 8);
        }
        CP_COMMIT();
    };

    {
#pragma unroll
        for (int i = 0; i < 16; i++) {
            int idx = tid + i * 256; int r = idx >> 6, c = idx & 63;
            cp16(smb + ((c >> 3) << 13) + SWZ(r * 128 + (c & 7) * 16),
                 x0g + (bm0 + (size_t)r) * DC + c * 8);
        }
        CP_COMMIT(); CP_WAIT0();
        __syncthreads();
    }

    auto run_gemm = [&](const __half* W, int pass, const __half* Wn, int passN) {
#pragma unroll
        for (int mi = 0; mi < 4; mi++)
#pragma unroll
            for (int ni = 0; ni < 4; ni++)
#pragma unroll
                for (int q = 0; q < 4; q++) acc[mi][ni][q] = 0.f;
        const __half* Wp  = W + (size_t)(pass * 256 + wid * 32) * DC;
        const __half* WpN = Wn ? Wn + (size_t)(passN * 256 + wid * 32) * DC : nullptr;
        if (!carried) { loadBw_at(Wp, 0, 0); loadBw_at(Wp, 1, 1); }
        uint32_t a[2][4][4], b[2][2][4];
        auto ldsmA = [&](int buf, int ks, uint32_t sA) {
#pragma unroll
            for (int mi = 0; mi < 4; mi++) {
                int m  = mi * 16 + (lane & 7) + ((lane >> 3) & 1) * 8;
                int kb = ks * 32 + (lane >> 4) * 16;
                ldsm4(a[buf][mi][0], a[buf][mi][1], a[buf][mi][2], a[buf][mi][3],
                      sA + SWZ(m * 128 + kb));
            }
        };
        auto ldsmB = [&](int buf, int ks, uint32_t sB) {
#pragma unroll
            for (int p = 0; p < 2; p++) {
                int n  = p * 16 + (lane >> 4) * 8 + (lane & 7);
                int kb = ks * 32 + ((lane >> 3) & 1) * 16;
                ldsm4(b[buf][p][0], b[buf][p][1], b[buf][p][2], b[buf][p][3],
                      sB + SWZ(n * 128 + kb));
            }
        };
#pragma unroll 1
        for (int kt = 0; kt < 8; kt++) {
            if (kt == 7) { if (WpN) { CP_WAIT1(); } else { CP_WAIT0(); } }
            else         { CP_WAIT1(); }
            const uint32_t sA = smb + kt * 8192;
            const uint32_t sB = sBw + (kt & 1) * 4096;
            if (kt == 0) ldsmA(0, 0, sA);
            ldsmB(0, 0, sB);
#pragma unroll
            for (int ks = 0; ks < 4; ks++) {
                const int cur = ks & 1;
                if (ks < 3) { ldsmA(cur ^ 1, ks + 1, sA); ldsmB(cur ^ 1, ks + 1, sB); }
                else if (kt < 7) ldsmA(cur ^ 1, 0, smb + (kt + 1) * 8192);
#pragma unroll
                for (int mi = 0; mi < 4; mi++)
#pragma unroll
                    for (int p = 0; p < 2; p++) {
                        mma16816(acc[mi][2 * p],     a[cur][mi], &b[cur][p][0]);
                        mma16816(acc[mi][2 * p + 1], a[cur][mi], &b[cur][p][2]);
                    }
            }
            if (kt < 6) loadBw_at(Wp, kt & 1, kt + 2);
            else if (kt == 6) { if (WpN) loadBw_at(WpN, 0, 0); }
            else { if (WpN) loadBw_at(WpN, 1, 1); }
        }
        carried = (WpN != nullptr);
    };

#pragma unroll 1
    for (int i = 0; i < 4; i++) {
        const __half* Wc = wh + W_UP + i * WSZ;
        const __half* Wn = (i < 3) ? wh + W_UP + (i + 1) * WSZ : nullptr;
#pragma unroll
        for (int z = 0; z < 8; z++) { rs[z] = 0.f; rq[z] = 0.f; }
#pragma unroll 1
        for (int pass = 0; pass < 2; pass++) {
            if (pass == 0) run_gemm(Wc, 0, Wc, 1);
            else           run_gemm(Wc, 1, Wn, 0);
#pragma unroll
            for (int ni = 0; ni < 4; ni++) {
                const int c = pass * 256 + wid * 32 + ni * 8 + 2 * t;
                const float2 bp = *(const float2*)(up_b + i * DC + c);
#pragma unroll
                for (int mi = 0; mi < 4; mi++)
#pragma unroll
                    for (int h = 0; h < 2; h++) {
                        const int row = mi * 16 + g + h * 8;
                        float vx = acc[mi][ni][2 * h]     + bp.x;
                        float vy = acc[mi][ni][2 * h + 1] + bp.y;
                        rs[mi * 2 + h] += vx + vy;
                        rq[mi * 2 + h] += vx * vx + vy * vy;
                        *(__half2*)(sm + YB_OFF + (uint32_t)row * YSTR + (uint32_t)(c >> 1) * 4) =
                            __floats2half2_rn(vx, vy);
                    }
            }
        }
#pragma unroll
        for (int r8 = 0; r8 < 8; r8++) {
            float s = rs[r8], q = rq[r8];
            s += __shfl_xor_sync(0xffffffffu, s, 1); q += __shfl_xor_sync(0xffffffffu, q, 1);
            s += __shfl_xor_sync(0xffffffffu, s, 2); q += __shfl_xor_sync(0xffffffffu, q, 2);
            if (t == 0) {
                const int row = (r8 >> 1) * 16 + g + (r8 & 1) * 8;
                part[row * 16 + wid * 2]     = s;
                part[row * 16 + wid * 2 + 1] = q;
            }
        }
        __syncthreads();
        if (tid < 64) {
            float s = 0.f, q = 0.f;
#pragma unroll
            for (int w = 0; w < 8; w++) { s += part[tid * 16 + w * 2]; q += part[tid * 16 + w * 2 + 1]; }
            const float mean = s * (1.f / 512.f);
            const float var  = q * (1.f / 512.f) - mean * mean;
            mrs[tid * 2]     = mean;
            mrs[tid * 2 + 1] = rsqrtf(var + 1e-5f);
        }
        __syncthreads();
        {
            const float2 lg = *(const float2*)(lng_all + i * DC + tid * 2);
            const float2 lb = *(const float2*)(lnb_all + i * DC + tid * 2);
            const uint32_t ablk = ((uint32_t)(tid >> 5) << 13);
            const uint32_t ain  = (uint32_t)((2 * tid) & 63) * 2;
            __half* outg = acts + i * ASZ;
#pragma unroll 4
            for (int row = 0; row < 64; row++) {
                __half2 hv = *(__half2*)(sm + YB_OFF + row * YSTR + tid * 4);
                float2 f = __half22float2(hv);
                const float mean = mrs[row * 2], rstd = mrs[row * 2 + 1];
                __half2 y2 = __floats2half2_rn((f.x - mean) * rstd * lg.x + lb.x,
                                               (f.y - mean) * rstd * lg.y + lb.y);
                *(__half2*)(outg + (bm0 + row) * DC + 2 * tid) = y2;
                *(__half2*)(sm + ablk + SWZ((uint32_t)row * 128 + ain)) = y2;
            }
            __syncthreads();
        }
    }
}

// ---------------------------------------------------------------------------
// kbig: K=2048 GEMM as 4 chunks of persistent-A(64KB) + per-warp B streaming
// (B panels chain across chunk boundaries). Warp tile 64x64. Bias -> half out.
//   AF32=1: A read fp32 (obs), converted per chunk; blockIdx.z = obs index.
// ---------------------------------------------------------------------------
template<int AF32>
__global__ void __launch_bounds__(256, 1) kbig(
    const void* Av, const __half* __restrict__ Wall,
    const float* __restrict__ bias, __half* out, int ldOut)
{
    extern __shared__ char sm[];
    const uint32_t smb = smem_u32(sm);
    const int tid = threadIdx.x, wid = tid >> 5, lane = tid & 31;
    const int g = lane >> 2, t = lane & 3;
    const size_t bm0 = (size_t)blockIdx.x * 64;
    const int o = blockIdx.z;
    const float*  Af = (const float*)Av + (size_t)o * TOK * DM;
    const __half* Ah = (const __half*)Av;
    const __half* Wp = Wall + (size_t)o * DC * DM + (size_t)(wid * 64) * DM;
    const float*  bp = bias + o * DC;
    __half* outp = out + o * 512;

    const uint32_t sBw = smb + KB_OFF + wid * 16384;   // 2 x 8KB panels

    float acc[4][8][4];
#pragma unroll
    for (int mi = 0; mi < 4; mi++)
#pragma unroll
        for (int ni = 0; ni < 8; ni++)
#pragma unroll
            for (int q = 0; q < 4; q++) acc[mi][ni][q] = 0.f;

    auto loadBw = [&](int buf, int gk) {   // 64 rows x 128B = 8KB panel
        const uint32_t sB = sBw + buf * 8192;
        const int k0 = gk * 64;
#pragma unroll
        for (int i = 0; i < 16; i++) {
            int idx = lane + i * 32; int r = idx >> 3, ch = idx & 7;
            cp16(sB + SWZ(r * 128 + ch * 16),
                 Wp + (size_t)r * DM + k0 + ch * 8);
        }
        CP_COMMIT();
    };

    auto loadA_chunk = [&](int c) {        // 64 rows x 512 halfs -> A smem
        if (AF32) {
#pragma unroll
            for (int i = 0; i < 16; i++) {
                int idx = tid + i * 256; int r = idx >> 6, cc = idx & 63;
                const float4* s = (const float4*)
                    (Af + (bm0 + r) * (size_t)DM + c * 512 + cc * 8);
                float4 x0 = s[0], x1 = s[1];
                __half2 h0 = __floats2half2_rn(x0.x, x0.y);
                __half2 h1 = __floats2half2_rn(x0.z, x0.w);
                __half2 h2 = __floats2half2_rn(x1.x, x1.y);
                __half2 h3 = __floats2half2_rn(x1.z, x1.w);
                asm volatile("st.shared.v4.b32 [%0], {%1,%2,%3,%4};"
                    :: "r"(smb + ((cc >> 3) << 13) + SWZ(r * 128 + (cc & 7) * 16)),
                       "r"(*(uint32_t*)&h0), "r"(*(uint32_t*)&h1),
                       "r"(*(uint32_t*)&h2), "r"(*(uint32_t*)&h3));
            }
        } else {
#pragma unroll
            for (int i = 0; i < 16; i++) {
                int idx = tid + i * 256; int r = idx >> 6, cc = idx & 63;
                cp16(smb + ((cc >> 3) << 13) + SWZ(r * 128 + (cc & 7) * 16),
                     Ah + (bm0 + (size_t)r) * DM + c * 512 + cc * 8);
            }
            CP_COMMIT();
        }
    };

#pragma unroll 1
    for (int c = 0; c < 4; c++) {
        __syncthreads();                    // all warps done reading prev A
        loadA_chunk(c);
        if (c == 0) { loadBw(0, 0); loadBw(1, 1); }
        CP_WAIT0();                         // drain A + pending B prefetches
        __syncthreads();
#pragma unroll 1
        for (int kt = 0; kt < 8; kt++) {
            if (c == 3 && kt == 7) { CP_WAIT0(); } else { CP_WAIT1(); }
            const uint32_t sA = smb + kt * 8192;
            const uint32_t sB = sBw + (kt & 1) * 8192;
#pragma unroll
            for (int ks = 0; ks < 4; ks++) {
                uint32_t a[4][4], b[4][4];
#pragma unroll
                for (int mi = 0; mi < 4; mi++) {
                    int m  = mi * 16 + (lane & 7) + ((lane >> 3) & 1) * 8;
                    int kb = ks * 32 + (lane >> 4) * 16;
                    ldsm4(a[mi][0], a[mi][1], a[mi][2], a[mi][3], sA + SWZ(m * 128 + kb));
                }
#pragma unroll
                for (int p = 0; p < 4; p++) {
                    int n  = p * 16 + (lane >> 4) * 8 + (lane & 7);
                    int kb = ks * 32 + ((lane >> 3) & 1) * 16;
                    ldsm4(b[p][0], b[p][1], b[p][2], b[p][3], sB + SWZ(n * 128 + kb));
                }
#pragma unroll
                for (int mi = 0; mi < 4; mi++)
#pragma unroll
                    for (int p = 0; p < 4; p++) {
                        mma16816(acc[mi][2 * p],     a[mi], &b[p][0]);
                        mma16816(acc[mi][2 * p + 1], a[mi], &b[p][2]);
                    }
            }
            if (kt < 6)      loadBw(kt & 1, c * 8 + kt + 2);
            else if (c < 3)  loadBw(kt & 1, (c + 1) * 8 + (kt - 6));
        }
    }

#pragma unroll
    for (int ni = 0; ni < 8; ni++) {
        const int c = wid * 64 + ni * 8 + 2 * t;
        const float2 b2 = *(const float2*)(bp + c);
#pragma unroll
        for (int mi = 0; mi < 4; mi++)
#pragma unroll
            for (int h = 0; h < 2; h++) {
                const int row = mi * 16 + g + h * 8;
                *(__half2*)(outp + (bm0 + row) * (size_t)ldOut + c) =
                    __floats2half2_rn(acc[mi][ni][2 * h] + b2.x,
                                      acc[mi][ni][2 * h + 1] + b2.y);
            }
    }
}

// ---------------------------------------------------------------------------
// Host orchestration (26 launches)
// ---------------------------------------------------------------------------
extern "C" void kernel_launch(void* const* d_in, const int* in_sizes, int n_in,
                              void* d_out, int out_size)
{
    const float* qwen   = (const float*)d_in[0];
    const float* obs    = (const float*)d_in[1];
    const float* proj_W = (const float*)d_in[2];
    const float* proj_b = (const float*)d_in[3];
    const float* fuse_W = (const float*)d_in[4];
    const float* fuse_b = (const float*)d_in[5];
    const float* up_W   = (const float*)d_in[6];
    const float* up_b   = (const float*)d_in[7];
    const float* lat_W  = (const float*)d_in[8];
    const float* lat_b  = (const float*)d_in[9];
    const float* plog   = (const float*)d_in[10];
    const float* ln_g   = (const float*)d_in[11];
    const float* ln_b   = (const float*)d_in[12];
    const float* down_W = (const float*)d_in[13];
    const float* down_b = (const float*)d_in[14];
    const float* out1_W = (const float*)d_in[15];
    const float* out1_b = (const float*)d_in[16];
    const float* out2_W = (const float*)d_in[17];
    const float* out2_b = (const float*)d_in[18];
    float* out = (float*)d_out;

    __half *wh, *cat, *x0, *acts, *hbuf;
    cudaGetSymbolAddress((void**)&wh,    g_wh);
    cudaGetSymbolAddress((void**)&cat,   g_cat);
    cudaGetSymbolAddress((void**)&x0,    g_x0);
    cudaGetSymbolAddress((void**)&acts,  g_acts);
    cudaGetSymbolAddress((void**)&hbuf,  g_h);

    cudaFuncSetAttribute(k512<M_UPD_P>,  cudaFuncAttributeMaxDynamicSharedMemorySize, SMEM_K);
    cudaFuncSetAttribute(k512<M_UPD_NP>, cudaFuncAttributeMaxDynamicSharedMemorySize, SMEM_K);
    cudaFuncSetAttribute(k512<M_GELU>,   cudaFuncAttributeMaxDynamicSharedMemorySize, SMEM_K);
    cudaFuncSetAttribute(k512<M_ADD>,    cudaFuncAttributeMaxDynamicSharedMemorySize, SMEM_K);
    cudaFuncSetAttribute(kfuse0,         cudaFuncAttributeMaxDynamicSharedMemorySize, SMEM_K);
    cudaFuncSetAttribute(kbig<0>,        cudaFuncAttributeMaxDynamicSharedMemorySize, SMEM_K);
    cudaFuncSetAttribute(kbig<1>,        cudaFuncAttributeMaxDynamicSharedMemorySize, SMEM_K);

    const dim3 blk(256);

    // 1) weight converts
    wconv<<<1024, blk>>>((const float2*)proj_W, (const float2*)fuse_W,
                         (const float2*)up_W,   (const float2*)lat_W,
                         (const float2*)down_W, (const float2*)out1_W,
                         (const float2*)out2_W, (__half2*)wh);

    // 2) input projections + fuse (chunked persistent-A kernels)
    kbig<1><<<dim3(TOK / 64, 1, 4), blk, SMEM_K>>>(
        obs, wh + W_PROJ, proj_b, cat, DM);
    kbig<0><<<dim3(TOK / 64, 1, 1), blk, SMEM_K>>>(
        cat, wh + W_FUSE, fuse_b, x0, DC);

    // 3) init sweep (fused)
    kfuse0<<<TOK / 64, blk, SMEM_K>>>(x0, acts, wh, up_b, ln_g, ln_b);

    // 4) settle
    for (int s = 0; s < 5; s++) {
        k512<M_UPD_P><<<TOK / 64, blk, SMEM_K>>>(
            acts + 1 * ASZ, x0, acts + 0 * ASZ,
            wh + W_DOWN + 1 * WSZ, wh + W_UP + 0 * WSZ, wh + W_LAT + 0 * WSZ,
            down_b + 1 * DC, up_b + 0 * DC, lat_b + 0 * DC,
            ln_g + 0 * DC, ln_b + 0 * DC, plog + 0 * DC,
            nullptr, acts + 0 * ASZ, DC);
        k512<M_UPD_P><<<TOK / 64, blk, SMEM_K>>>(
            acts + 2 * ASZ, acts + 0 * ASZ, acts + 1 * ASZ,
            wh + W_DOWN + 2 * WSZ, wh + W_UP + 1 * WSZ, wh + W_LAT + 1 * WSZ,
            down_b + 2 * DC, up_b + 1 * DC, lat_b + 1 * DC,
            ln_g + 1 * DC, ln_b + 1 * DC, plog + 1 * DC,
            nullptr, acts + 1 * ASZ, DC);
        k512<M_UPD_NP><<<TOK / 64, blk, SMEM_K>>>(
            nullptr, acts + 1 * ASZ, acts + 2 * ASZ,
            nullptr, wh + W_UP + 2 * WSZ, wh + W_LAT + 2 * WSZ,
            nullptr, up_b + 2 * DC, lat_b + 2 * DC,
            ln_g + 2 * DC, ln_b + 2 * DC, plog + 2 * DC,
            nullptr, acts + 2 * ASZ, DC);
        k512<M_UPD_NP><<<TOK / 64, blk, SMEM_K>>>(
            nullptr, acts + 2 * ASZ, acts + 3 * ASZ,
            nullptr, wh + W_UP + 3 * WSZ, wh + W_LAT + 3 * WSZ,
            nullptr, up_b + 3 * DC, lat_b + 3 * DC,
            ln_g + 3 * DC, ln_b + 3 * DC, plog + 3 * DC,
            nullptr, acts + 3 * ASZ, DC);
    }

    // 5) head
    k512<M_GELU><<<TOK / 64, blk, SMEM_K>>>(
        nullptr, acts + 3 * ASZ, nullptr,
        nullptr, wh + W_OUT1, nullptr,
        nullptr, out1_b, nullptr,
        nullptr, nullptr, nullptr,
        nullptr, hbuf, DC);
    k512<M_ADD><<<dim3(TOK / 64, 4), blk, SMEM_K>>>(
        nullptr, hbuf, nullptr,
        nullptr, wh + W_OUT2, nullptr,
        nullptr, out2_b, nullptr,
        nullptr, nullptr, nullptr,
        qwen, out, DM);
    (void)in_sizes; (void)n_in; (void)out_size;
}

// round 16
// speedup vs baseline: 1.0354x; 1.0354x over previous
#include <cuda_runtime.h>
#include <cuda_fp16.h>
#include <cstdint>
#include <cstddef>

// ---------------------------------------------------------------------------
// Problem constants
// ---------------------------------------------------------------------------
#define TOK   8192
#define DC    512
#define DM    2048
#define ASZ   ((size_t)TOK * DC)
#define WSZ   ((size_t)DC * DC)

// ---- shared smem layout (k512 / kfuse0) -------------------------------------
#define KB_OFF     65536
#define YB_OFF     131072
#define YSTR       1040
#define SCR_OFF    198656
#define MRS_OFF    202752
#define SMEM_K     204800

// ---- gemm_big smem layout ---------------------------------------------------
#define BA_BYTES   8192
#define BB_OFF     16384
#define BB_BYTES   65536
#define SMEM_BIG   147456

#define SWZ(x) ((x) ^ (((x) >> 3) & 0x70))

// ---------------------------------------------------------------------------
// Device scratch
// ---------------------------------------------------------------------------
#define W_PROJ 0
#define W_FUSE 4194304
#define W_UP   5242880
#define W_LAT  6291456
#define W_DOWN 7340032
#define W_OUT1 8126464
#define W_OUT2 8388608
__device__ __half g_wh[9437184];
__device__ __half g_cat [(size_t)TOK * DM];
__device__ __half g_x0  [TOK * DC];
__device__ __half g_acts[4 * TOK * DC];
__device__ __half g_h   [TOK * DC];

// ---------------------------------------------------------------------------
// PTX helpers
// ---------------------------------------------------------------------------
__device__ __forceinline__ uint32_t smem_u32(const void* p) {
    uint32_t a;
    asm("{ .reg .u64 t; cvta.to.shared.u64 t, %1; cvt.u32.u64 %0, t; }"
        : "=r"(a) : "l"(p));
    return a;
}
__device__ __forceinline__ void cp16(uint32_t d, const void* s) {
    asm volatile("cp.async.cg.shared.global [%0], [%1], 16;\n" :: "r"(d), "l"(s));
}
__device__ __forceinline__ void ldsm4(uint32_t& r0, uint32_t& r1,
                                      uint32_t& r2, uint32_t& r3, uint32_t a) {
    asm volatile("ldmatrix.sync.aligned.m8n8.x4.shared.b16 {%0,%1,%2,%3}, [%4];"
                 : "=r"(r0), "=r"(r1), "=r"(r2), "=r"(r3) : "r"(a));
}
__device__ __forceinline__ void mma16816(float* c, const uint32_t* a, const uint32_t* b) {
    asm volatile(
        "mma.sync.aligned.m16n8k16.row.col.f32.f16.f16.f32 "
        "{%0,%1,%2,%3}, {%4,%5,%6,%7}, {%8,%9}, {%0,%1,%2,%3};"
        : "+f"(c[0]), "+f"(c[1]), "+f"(c[2]), "+f"(c[3])
        : "r"(a[0]), "r"(a[1]), "r"(a[2]), "r"(a[3]), "r"(b[0]), "r"(b[1]));
}
#define CP_COMMIT() asm volatile("cp.async.commit_group;\n" ::: "memory")
#define CP_WAIT0()  asm volatile("cp.async.wait_group 0;\n" ::: "memory")
#define CP_WAIT1()  asm volatile("cp.async.wait_group 1;\n" ::: "memory")

enum { M_LN = 0, M_UPD_P = 1, M_UPD_NP = 2, M_GELU = 3, M_ADD = 4 };

// ---------------------------------------------------------------------------
// Merged weight fp32 -> fp16 convert
// ---------------------------------------------------------------------------
__global__ void wconv(const float2* p, const float2* f, const float2* u,
                      const float2* l, const float2* dw, const float2* o1,
                      const float2* o2, __half2* dst)
{
    const size_t N0 = 2097152, N1 = 524288, N2 = 524288, N3 = 524288,
                 N4 = 393216,  N5 = 131072, N6 = 524288;
    const size_t T = N0 + N1 + N2 + N3 + N4 + N5 + N6;
    size_t i = (size_t)blockIdx.x * blockDim.x + threadIdx.x;
    size_t st = (size_t)gridDim.x * blockDim.x;
    for (; i < T; i += st) {
        size_t j = i; const float2* s;
        if (j < N0) s = p + j;
        else { j -= N0; if (j < N1) s = f + j;
        else { j -= N1; if (j < N2) s = u + j;
        else { j -= N2; if (j < N3) s = l + j;
        else { j -= N3; if (j < N4) s = dw + j;
        else { j -= N4; if (j < N5) s = o1 + j;
        else { j -= N5; s = o2 + j; }}}}}}
        dst[i] = __float22half2_rn(*s);
    }
}

// ---------------------------------------------------------------------------
// k512 (R14 + shadowed interior loadA ONLY): CTA tile 64x512 two passes,
// warp tile 64x32, per-warp B double buffer, register stash, ybuf LN.
// ---------------------------------------------------------------------------
template<int MODE>
__global__ void __launch_bounds__(256, 1) k512(
    const __half* __restrict__ A1, const __half* __restrict__ A2,
    const __half* __restrict__ A3,
    const __half* __restrict__ W1, const __half* __restrict__ W2,
    const __half* __restrict__ W3,
    const float* __restrict__ b1, const float* __restrict__ b2,
    const float* __restrict__ b3,
    const float* __restrict__ lng, const float* __restrict__ lnb,
    const float* __restrict__ plog,
    const float* __restrict__ qwen, void* outv, int ldOut)
{
    extern __shared__ char sm[];
    const uint32_t smb = smem_u32(sm);
    const int tid = threadIdx.x, wid = tid >> 5, lane = tid & 31;
    const int g = lane >> 2, t = lane & 3;
    const size_t bm0 = (size_t)blockIdx.x * 64;
    const int colOff = blockIdx.y * 512;
    if (MODE == M_ADD) { W2 += (size_t)colOff * DC; b2 += colOff; }

    float acc[4][4][4];
    uint32_t stash[2][4][4][2];
    float rs[8], rq[8];
    float* part = (float*)(sm + SCR_OFF);
    float* mrs  = (float*)(sm + MRS_OFF);
    const uint32_t sBw = smb + KB_OFF + wid * 8192;

    auto loadA_issue = [&](const __half* Ap) {
#pragma unroll
        for (int i = 0; i < 16; i++) {
            int idx = tid + i * 256; int r = idx >> 6, c = idx & 63;
            cp16(smb + ((c >> 3) << 13) + SWZ(r * 128 + (c & 7) * 16),
                 Ap + (bm0 + (size_t)r) * DC + c * 8);
        }
        CP_COMMIT();
    };
    auto loadA = [&](const __half* Ap) {
        __syncthreads();
        loadA_issue(Ap);
        CP_WAIT0(); __syncthreads();
    };

    auto run_gemm = [&](const __half* W, int pass) {
#pragma unroll
        for (int mi = 0; mi < 4; mi++)
#pragma unroll
            for (int ni = 0; ni < 4; ni++)
#pragma unroll
                for (int q = 0; q < 4; q++) acc[mi][ni][q] = 0.f;
        const __half* Wp = W + (size_t)(pass * 256 + wid * 32) * DC;
        auto loadBw = [&](int buf, int kt) {
            const uint32_t sB = sBw + buf * 4096;
            const int k0 = kt * 64;
#pragma unroll
            for (int i = 0; i < 8; i++) {
                int idx = lane + i * 32; int r = idx >> 3, ch = idx & 7;
                cp16(sB + SWZ(r * 128 + ch * 16),
                     Wp + (size_t)r * DC + k0 + ch * 8);
            }
            CP_COMMIT();
        };
        loadBw(0, 0);
        loadBw(1, 1);
        uint32_t a[2][4][4], b[2][2][4];
        auto ldsmA = [&](int buf, int ks, uint32_t sA) {
#pragma unroll
            for (int mi = 0; mi < 4; mi++) {
                int m  = mi * 16 + (lane & 7) + ((lane >> 3) & 1) * 8;
                int kb = ks * 32 + (lane >> 4) * 16;
                ldsm4(a[buf][mi][0], a[buf][mi][1], a[buf][mi][2], a[buf][mi][3],
                      sA + SWZ(m * 128 + kb));
            }
        };
        auto ldsmB = [&](int buf, int ks, uint32_t sB) {
#pragma unroll
            for (int p = 0; p < 2; p++) {
                int n  = p * 16 + (lane >> 4) * 8 + (lane & 7);
                int kb = ks * 32 + ((lane >> 3) & 1) * 16;
                ldsm4(b[buf][p][0], b[buf][p][1], b[buf][p][2], b[buf][p][3],
                      sB + SWZ(n * 128 + kb));
            }
        };
#pragma unroll 1
        for (int kt = 0; kt < 8; kt++) {
            if (kt == 7) { CP_WAIT0(); } else { CP_WAIT1(); }
            const uint32_t sA = smb + kt * 8192;
            const uint32_t sB = sBw + (kt & 1) * 4096;
            if (kt == 0) ldsmA(0, 0, sA);
            ldsmB(0, 0, sB);
#pragma unroll
            for (int ks = 0; ks < 4; ks++) {
                const int cur = ks & 1;
                if (ks < 3) { ldsmA(cur ^ 1, ks + 1, sA); ldsmB(cur ^ 1, ks + 1, sB); }
                else if (kt < 7) ldsmA(cur ^ 1, 0, smb + (kt + 1) * 8192);
#pragma unroll
                for (int mi = 0; mi < 4; mi++)
#pragma unroll
                    for (int p = 0; p < 2; p++) {
                        mma16816(acc[mi][2 * p],     a[cur][mi], &b[cur][p][0]);
                        mma16816(acc[mi][2 * p + 1], a[cur][mi], &b[cur][p][2]);
                    }
            }
            if (kt < 6) loadBw(kt & 1, kt + 2);
        }
    };

    auto zero_stats = [&]() {
#pragma unroll
        for (int i = 0; i < 8; i++) { rs[i] = 0.f; rq[i] = 0.f; }
    };
    auto ln_stats = [&]() {
#pragma unroll
        for (int r8 = 0; r8 < 8; r8++) {
            float s = rs[r8], q = rq[r8];
            s += __shfl_xor_sync(0xffffffffu, s, 1); q += __shfl_xor_sync(0xffffffffu, q, 1);
            s += __shfl_xor_sync(0xffffffffu, s, 2); q += __shfl_xor_sync(0xffffffffu, q, 2);
            if (t == 0) {
                const int row = (r8 >> 1) * 16 + g + (r8 & 1) * 8;
                part[row * 16 + wid * 2]     = s;
                part[row * 16 + wid * 2 + 1] = q;
            }
        }
        __syncthreads();
        if (tid < 64) {
            float s = 0.f, q = 0.f;
#pragma unroll
            for (int w = 0; w < 8; w++) { s += part[tid * 16 + w * 2]; q += part[tid * 16 + w * 2 + 1]; }
            const float mean = s * (1.f / 512.f);
            const float var  = q * (1.f / 512.f) - mean * mean;
            mrs[tid * 2]     = mean;
            mrs[tid * 2 + 1] = rsqrtf(var + 1e-5f);
        }
        __syncthreads();
    };

    __half* outH = (__half*)outv;
    float*  outF = (float*)outv;

    auto flatnorm = [&](__half* outg) {
        const float2 lgv = *(const float2*)(lng + tid * 2);
        const float2 lbv = *(const float2*)(lnb + tid * 2);
#pragma unroll 4
        for (int row = 0; row < 64; row++) {
            __half2 hv = *(__half2*)(sm + YB_OFF + row * YSTR + tid * 4);
            float2 f = __half22float2(hv);
            const float mean = mrs[row * 2], rstd = mrs[row * 2 + 1];
            *(__half2*)(outg + (bm0 + row) * DC + 2 * tid) =
                __floats2half2_rn((f.x - mean) * rstd * lgv.x + lbv.x,
                                  (f.y - mean) * rstd * lgv.y + lbv.y);
        }
    };

    // ---------------- phase 1: pred (UPD_P only) ------------------------------
    if (MODE == M_UPD_P) {
        loadA(A1);
#pragma unroll 1
        for (int pass = 0; pass < 2; pass++) {
            run_gemm(W1, pass);
            if (pass == 1) { __syncthreads(); loadA_issue(A2); }  // shadow A2
#pragma unroll
            for (int ni = 0; ni < 4; ni++) {
                const int c = pass * 256 + wid * 32 + ni * 8 + 2 * t;
                const float2 bp = *(const float2*)(b1 + c);
#pragma unroll
                for (int mi = 0; mi < 4; mi++)
#pragma unroll
                    for (int h = 0; h < 2; h++) {
                        __half2 hv = __floats2half2_rn(acc[mi][ni][2 * h] + bp.x,
                                                       acc[mi][ni][2 * h + 1] + bp.y);
                        stash[pass][mi][ni][h] = *(uint32_t*)&hv;
                    }
            }
        }
        CP_WAIT0(); __syncthreads();
    } else {
        loadA(A2);
    }

    // ---------------- phase 2: main / comp GEMM -------------------------------
    if (MODE == M_LN || MODE == M_UPD_P || MODE == M_UPD_NP) {
        zero_stats();
#pragma unroll 1
        for (int pass = 0; pass < 2; pass++) {
            run_gemm(W2, pass);
#pragma unroll
            for (int ni = 0; ni < 4; ni++) {
                const int c = pass * 256 + wid * 32 + ni * 8 + 2 * t;
                const float2 bp = *(const float2*)(b2 + c);
                const uint32_t ya = smb + YB_OFF + (uint32_t)(c >> 1) * 4;
#pragma unroll
                for (int mi = 0; mi < 4; mi++)
#pragma unroll
                    for (int h = 0; h < 2; h++) {
                        const int row = mi * 16 + g + h * 8;
                        float vx = acc[mi][ni][2 * h]     + bp.x;
                        float vy = acc[mi][ni][2 * h + 1] + bp.y;
                        rs[mi * 2 + h] += vx + vy;
                        rq[mi * 2 + h] += vx * vx + vy * vy;
                        __half2 hv = __floats2half2_rn(vx, vy);
                        *(__half2*)(sm + (ya - smb) + (uint32_t)row * YSTR) = hv;
                    }
            }
        }
        ln_stats();
        if (MODE == M_LN) {
            flatnorm(outH);
        } else {
            loadA_issue(A3);                 // shadow A3 behind normalize-stash
#pragma unroll
            for (int pass = 0; pass < 2; pass++)
#pragma unroll
                for (int ni = 0; ni < 4; ni++) {
                    const int c = pass * 256 + wid * 32 + ni * 8 + 2 * t;
                    const float2 lgc = *(const float2*)(lng + c);
                    const float2 lbc = *(const float2*)(lnb + c);
#pragma unroll
                    for (int mi = 0; mi < 4; mi++)
#pragma unroll
                        for (int h = 0; h < 2; h++) {
                            const int row = mi * 16 + g + h * 8;
                            const float mean = mrs[row * 2], rstd = mrs[row * 2 + 1];
                            __half2 hv = *(__half2*)(sm + YB_OFF + row * YSTR + (c >> 1) * 4);
                            float2 f = __half22float2(hv);
                            const float cx = (f.x - mean) * rstd * lgc.x + lbc.x;
                            const float cy = (f.y - mean) * rstd * lgc.y + lbc.y;
                            __half2 sv;
                            if (MODE == M_UPD_P) {
                                float2 pf = __half22float2(*(__half2*)&stash[pass][mi][ni][h]);
                                sv = __floats2half2_rn(cx - pf.x, cy - pf.y);
                            } else {
                                sv = __floats2half2_rn(cx, cy);
                            }
                            stash[pass][mi][ni][h] = *(uint32_t*)&sv;
                        }
                }
            CP_WAIT0(); __syncthreads();
        }
    } else {
#pragma unroll 1
        for (int pass = 0; pass < 2; pass++) {
            run_gemm(W2, pass);
#pragma unroll
            for (int ni = 0; ni < 4; ni++) {
                const int c = pass * 256 + wid * 32 + ni * 8 + 2 * t;
                const float2 bp = *(const float2*)(b2 + c);
#pragma unroll
                for (int mi = 0; mi < 4; mi++)
#pragma unroll
                    for (int h = 0; h < 2; h++) {
                        const int row = mi * 16 + g + h * 8;
                        float vx = acc[mi][ni][2 * h]     + bp.x;
                        float vy = acc[mi][ni][2 * h + 1] + bp.y;
                        if (MODE == M_GELU) {
                            vx = 0.5f * vx * (1.f + erff(vx * 0.70710678118f));
                            vy = 0.5f * vy * (1.f + erff(vy * 0.70710678118f));
                            *(__half2*)(outH + (bm0 + row) * (size_t)ldOut + c) =
                                __floats2half2_rn(vx, vy);
                        } else {
                            const float2 qv = *(const float2*)
                                (qwen + (bm0 + row) * (size_t)DM + colOff + c);
                            float2 o; o.x = vx + qv.x; o.y = vy + qv.y;
                            *(float2*)(outF + (bm0 + row) * (size_t)ldOut + colOff + c) = o;
                        }
                    }
            }
        }
    }

    // ---------------- phase 3: lateral GEMM + update + LN ---------------------
    if (MODE == M_UPD_P || MODE == M_UPD_NP) {
        zero_stats();
#pragma unroll 1
        for (int pass = 0; pass < 2; pass++) {
            run_gemm(W3, pass);
#pragma unroll
            for (int ni = 0; ni < 4; ni++) {
                const int c = pass * 256 + wid * 32 + ni * 8 + 2 * t;
                const float2 bp = *(const float2*)(b3 + c);
                const float px = 1.f / (1.f + __expf(-plog[c]));
                const float py = 1.f / (1.f + __expf(-plog[c + 1]));
                const uint32_t cblk = ((uint32_t)(c >> 6) << 13);
                const uint32_t cin  = (uint32_t)(c & 63) * 2;
#pragma unroll
                for (int mi = 0; mi < 4; mi++)
#pragma unroll
                    for (int h = 0; h < 2; h++) {
                        const int row = mi * 16 + g + h * 8;
                        __half2 ah = *(__half2*)(sm + cblk + SWZ((uint32_t)row * 128 + cin));
                        float2 af = __half22float2(ah);
                        float2 sf = __half22float2(*(__half2*)&stash[pass][mi][ni][h]);
                        float dx, dy;
                        if (MODE == M_UPD_P) { dx = sf.x; dy = sf.y; }
                        else                 { dx = sf.x - af.x; dy = sf.y - af.y; }
                        const float yx =
                            af.x + 0.5f * px * dx + 0.1f * (acc[mi][ni][2 * h] + bp.x);
                        const float yy =
                            af.y + 0.5f * py * dy + 0.1f * (acc[mi][ni][2 * h + 1] + bp.y);
                        rs[mi * 2 + h] += yx + yy;
                        rq[mi * 2 + h] += yx * yx + yy * yy;
                        *(__half2*)(sm + YB_OFF + (uint32_t)row * YSTR + (uint32_t)(c >> 1) * 4) =
                            __floats2half2_rn(yx, yy);
                    }
            }
        }
        ln_stats();
        flatnorm(outH);
    }
}

// ---------------------------------------------------------------------------
// kfuse0: fused INIT sweep (verified R14 kernel, unchanged).
// ---------------------------------------------------------------------------
__global__ void __launch_bounds__(256, 1) kfuse0(
    const __half* __restrict__ x0g, __half* acts,
    const __half* __restrict__ wh, const float* __restrict__ up_b,
    const float* __restrict__ lng_all, const float* __restrict__ lnb_all)
{
    extern __shared__ char sm[];
    const uint32_t smb = smem_u32(sm);
    const int tid = threadIdx.x, wid = tid >> 5, lane = tid & 31;
    const int g = lane >> 2, t = lane & 3;
    const size_t bm0 = (size_t)blockIdx.x * 64;

    float acc[4][4][4];
    float rs[8], rq[8];
    float* part = (float*)(sm + SCR_OFF);
    float* mrs  = (float*)(sm + MRS_OFF);
    const uint32_t sBw = smb + KB_OFF + wid * 8192;
    bool carried = false;

    auto loadBw_at = [&](const __half* Wp, int buf, int kt) {
        const uint32_t sB = sBw + buf * 4096;
        const int k0 = kt * 64;
#pragma unroll
        for (int i = 0; i < 8; i++) {
            int idx = lane + i * 32; int r = idx >> 3, ch = idx & 7;
            cp16(sB + SWZ(r * 128 + ch * 16),
                 Wp + (size_t)r * DC + k0 + ch * 8);
        }
        CP_COMMIT();
    };

    {
#pragma unroll
        for (int i = 0; i < 16; i++) {
            int idx = tid + i * 256; int r = idx >> 6, c = idx & 63;
            cp16(smb + ((c >> 3) << 13) + SWZ(r * 128 + (c & 7) * 16),
                 x0g + (bm0 + (size_t)r) * DC + c * 8);
        }
        CP_COMMIT(); CP_WAIT0();
        __syncthreads();
    }

    auto run_gemm = [&](const __half* W, int pass, const __half* Wn, int passN) {
#pragma unroll
        for (int mi = 0; mi < 4; mi++)
#pragma unroll
            for (int ni = 0; ni < 4; ni++)
#pragma unroll
                for (int q = 0; q < 4; q++) acc[mi][ni][q] = 0.f;
        const __half* Wp  = W + (size_t)(pass * 256 + wid * 32) * DC;
        const __half* WpN = Wn ? Wn + (size_t)(passN * 256 + wid * 32) * DC : nullptr;
        if (!carried) { loadBw_at(Wp, 0, 0); loadBw_at(Wp, 1, 1); }
        uint32_t a[2][4][4], b[2][2][4];
        auto ldsmA = [&](int buf, int ks, uint32_t sA) {
#pragma unroll
            for (int mi = 0; mi < 4; mi++) {
                int m  = mi * 16 + (lane & 7) + ((lane >> 3) & 1) * 8;
                int kb = ks * 32 + (lane >> 4) * 16;
                ldsm4(a[buf][mi][0], a[buf][mi][1], a[buf][mi][2], a[buf][mi][3],
                      sA + SWZ(m * 128 + kb));
            }
        };
        auto ldsmB = [&](int buf, int ks, uint32_t sB) {
#pragma unroll
            for (int p = 0; p < 2; p++) {
                int n  = p * 16 + (lane >> 4) * 8 + (lane & 7);
                int kb = ks * 32 + ((lane >> 3) & 1) * 16;
                ldsm4(b[buf][p][0], b[buf][p][1], b[buf][p][2], b[buf][p][3],
                      sB + SWZ(n * 128 + kb));
            }
        };
#pragma unroll 1
        for (int kt = 0; kt < 8; kt++) {
            if (kt == 7) { if (WpN) { CP_WAIT1(); } else { CP_WAIT0(); } }
            else         { CP_WAIT1(); }
            const uint32_t sA = smb + kt * 8192;
            const uint32_t sB = sBw + (kt & 1) * 4096;
            if (kt == 0) ldsmA(0, 0, sA);
            ldsmB(0, 0, sB);
#pragma unroll
            for (int ks = 0; ks < 4; ks++) {
                const int cur = ks & 1;
                if (ks < 3) { ldsmA(cur ^ 1, ks + 1, sA); ldsmB(cur ^ 1, ks + 1, sB); }
                else if (kt < 7) ldsmA(cur ^ 1, 0, smb + (kt + 1) * 8192);
#pragma unroll
                for (int mi = 0; mi < 4; mi++)
#pragma unroll
                    for (int p = 0; p < 2; p++) {
                        mma16816(acc[mi][2 * p],     a[cur][mi], &b[cur][p][0]);
                        mma16816(acc[mi][2 * p + 1], a[cur][mi], &b[cur][p][2]);
                    }
            }
            if (kt < 6) loadBw_at(Wp, kt & 1, kt + 2);
            else if (kt == 6) { if (WpN) loadBw_at(WpN, 0, 0); }
            else { if (WpN) loadBw_at(WpN, 1, 1); }
        }
        carried = (WpN != nullptr);
    };

#pragma unroll 1
    for (int i = 0; i < 4; i++) {
        const __half* Wc = wh + W_UP + i * WSZ;
        const __half* Wn = (i < 3) ? wh + W_UP + (i + 1) * WSZ : nullptr;
#pragma unroll
        for (int z = 0; z < 8; z++) { rs[z] = 0.f; rq[z] = 0.f; }
#pragma unroll 1
        for (int pass = 0; pass < 2; pass++) {
            if (pass == 0) run_gemm(Wc, 0, Wc, 1);
            else           run_gemm(Wc, 1, Wn, 0);
#pragma unroll
            for (int ni = 0; ni < 4; ni++) {
                const int c = pass * 256 + wid * 32 + ni * 8 + 2 * t;
                const float2 bp = *(const float2*)(up_b + i * DC + c);
#pragma unroll
                for (int mi = 0; mi < 4; mi++)
#pragma unroll
                    for (int h = 0; h < 2; h++) {
                        const int row = mi * 16 + g + h * 8;
                        float vx = acc[mi][ni][2 * h]     + bp.x;
                        float vy = acc[mi][ni][2 * h + 1] + bp.y;
                        rs[mi * 2 + h] += vx + vy;
                        rq[mi * 2 + h] += vx * vx + vy * vy;
                        *(__half2*)(sm + YB_OFF + (uint32_t)row * YSTR + (uint32_t)(c >> 1) * 4) =
                            __floats2half2_rn(vx, vy);
                    }
            }
        }
#pragma unroll
        for (int r8 = 0; r8 < 8; r8++) {
            float s = rs[r8], q = rq[r8];
            s += __shfl_xor_sync(0xffffffffu, s, 1); q += __shfl_xor_sync(0xffffffffu, q, 1);
            s += __shfl_xor_sync(0xffffffffu, s, 2); q += __shfl_xor_sync(0xffffffffu, q, 2);
            if (t == 0) {
                const int row = (r8 >> 1) * 16 + g + (r8 & 1) * 8;
                part[row * 16 + wid * 2]     = s;
                part[row * 16 + wid * 2 + 1] = q;
            }
        }
        __syncthreads();
        if (tid < 64) {
            float s = 0.f, q = 0.f;
#pragma unroll
            for (int w = 0; w < 8; w++) { s += part[tid * 16 + w * 2]; q += part[tid * 16 + w * 2 + 1]; }
            const float mean = s * (1.f / 512.f);
            const float var  = q * (1.f / 512.f) - mean * mean;
            mrs[tid * 2]     = mean;
            mrs[tid * 2 + 1] = rsqrtf(var + 1e-5f);
        }
        __syncthreads();
        {
            const float2 lg = *(const float2*)(lng_all + i * DC + tid * 2);
            const float2 lb = *(const float2*)(lnb_all + i * DC + tid * 2);
            const uint32_t ablk = ((uint32_t)(tid >> 5) << 13);
            const uint32_t ain  = (uint32_t)((2 * tid) & 63) * 2;
            __half* outg = acts + i * ASZ;
#pragma unroll 4
            for (int row = 0; row < 64; row++) {
                __half2 hv = *(__half2*)(sm + YB_OFF + row * YSTR + tid * 4);
                float2 f = __half22float2(hv);
                const float mean = mrs[row * 2], rstd = mrs[row * 2 + 1];
                __half2 y2 = __floats2half2_rn((f.x - mean) * rstd * lg.x + lb.x,
                                               (f.y - mean) * rstd * lg.y + lb.y);
                *(__half2*)(outg + (bm0 + row) * DC + 2 * tid) = y2;
                *(__half2*)(sm + ablk + SWZ((uint32_t)row * 128 + ain)) = y2;
            }
            __syncthreads();
        }
    }
}

// ---------------------------------------------------------------------------
// gemm_big: K=2048 GEMM, bias epilogue, half output (proven R4/R14 config).
// ---------------------------------------------------------------------------
template<int AF32>
__global__ void __launch_bounds__(256, 1) gemm_big(
    const void* Av, const __half* __restrict__ Wall,
    const float* __restrict__ bias, __half* out, int ldOut)
{
    extern __shared__ char sm[];
    const uint32_t smb = smem_u32(sm);
    const int tid = threadIdx.x, wid = tid >> 5, lane = tid & 31;
    const int g = lane >> 2, t = lane & 3;
    const size_t bm0 = (size_t)blockIdx.x * 64;
    const int o = blockIdx.z;
    const float*  Af = (const float*)Av + (size_t)o * TOK * DM;
    const __half* Ah = (const __half*)Av;
    const __half* W  = Wall + (size_t)o * DC * DM;
    const float*  bp = bias + o * DC;
    __half* outp = out + o * 512;

    float acc[4][8][4];
#pragma unroll
    for (int mi = 0; mi < 4; mi++)
#pragma unroll
        for (int ni = 0; ni < 8; ni++)
#pragma unroll
            for (int q = 0; q < 4; q++) acc[mi][ni][q] = 0.f;

    float fr[16];
    auto ldgA = [&](int kt) {
        const int k0 = kt * 64;
#pragma unroll
        for (int i = 0; i < 2; i++) {
            int idx = tid + i * 256; int r = idx >> 3, ch = idx & 7;
            const float4* s = (const float4*)(Af + (bm0 + r) * (size_t)DM + k0 + ch * 8);
            float4 x0 = s[0], x1 = s[1];
            fr[i * 8 + 0] = x0.x; fr[i * 8 + 1] = x0.y; fr[i * 8 + 2] = x0.z; fr[i * 8 + 3] = x0.w;
            fr[i * 8 + 4] = x1.x; fr[i * 8 + 5] = x1.y; fr[i * 8 + 6] = x1.z; fr[i * 8 + 7] = x1.w;
        }
    };
    auto stsA = [&](int buf) {
        const uint32_t sA = smb + buf * BA_BYTES;
#pragma unroll
        for (int i = 0; i < 2; i++) {
            int idx = tid + i * 256; int r = idx >> 3, ch = idx & 7;
            __half2 h0 = __floats2half2_rn(fr[i * 8 + 0], fr[i * 8 + 1]);
            __half2 h1 = __floats2half2_rn(fr[i * 8 + 2], fr[i * 8 + 3]);
            __half2 h2 = __floats2half2_rn(fr[i * 8 + 4], fr[i * 8 + 5]);
            __half2 h3 = __floats2half2_rn(fr[i * 8 + 6], fr[i * 8 + 7]);
            asm volatile("st.shared.v4.b32 [%0], {%1,%2,%3,%4};"
                :: "r"(sA + SWZ(r * 128 + ch * 16)),
                   "r"(*(uint32_t*)&h0), "r"(*(uint32_t*)&h1),
                   "r"(*(uint32_t*)&h2), "r"(*(uint32_t*)&h3));
        }
    };
    auto loadAh = [&](int buf, int kt) {
        const uint32_t sA = smb + buf * BA_BYTES;
        const int k0 = kt * 64;
#pragma unroll
        for (int i = 0; i < 2; i++) {
            int idx = tid + i * 256; int r = idx >> 3, ch = idx & 7;
            cp16(sA + SWZ(r * 128 + ch * 16), Ah + (bm0 + r) * (size_t)DM + k0 + ch * 8);
        }
    };
    auto loadB = [&](int buf, int kt) {
        const uint32_t sB = smb + BB_OFF + buf * BB_BYTES;
        const int k0 = kt * 64;
#pragma unroll
        for (int i = 0; i < 16; i++) {
            int idx = tid + i * 256; int r = idx >> 3, ch = idx & 7;
            cp16(sB + SWZ(r * 128 + ch * 16), W + (size_t)r * DM + k0 + ch * 8);
        }
    };

    if (AF32) ldgA(0); else loadAh(0, 0);
    loadB(0, 0);
    CP_COMMIT();
    for (int kt = 0; kt < 32; kt++) {
        CP_WAIT0();
        __syncthreads();
        if (AF32) {
            stsA(kt & 1);
            if (kt < 31) ldgA(kt + 1);
        }
        if (kt < 31) {
            if (!AF32) loadAh((kt + 1) & 1, kt + 1);
            loadB((kt + 1) & 1, kt + 1);
        }
        CP_COMMIT();
        if (AF32) __syncthreads();
        const uint32_t sA = smb + (kt & 1) * BA_BYTES;
        const uint32_t sB = smb + BB_OFF + (kt & 1) * BB_BYTES;
#pragma unroll
        for (int ks = 0; ks < 4; ks++) {
            uint32_t a[4][4], b[4][4];
#pragma unroll
            for (int mi = 0; mi < 4; mi++) {
                int m  = mi * 16 + (lane & 7) + ((lane >> 3) & 1) * 8;
                int kb = ks * 32 + (lane >> 4) * 16;
                ldsm4(a[mi][0], a[mi][1], a[mi][2], a[mi][3], sA + SWZ(m * 128 + kb));
            }
#pragma unroll
            for (int p = 0; p < 4; p++) {
                int n  = wid * 64 + p * 16 + (lane >> 4) * 8 + (lane & 7);
                int kb = ks * 32 + ((lane >> 3) & 1) * 16;
                ldsm4(b[p][0], b[p][1], b[p][2], b[p][3], sB + SWZ(n * 128 + kb));
            }
#pragma unroll
            for (int mi = 0; mi < 4; mi++)
#pragma unroll
                for (int p = 0; p < 4; p++) {
                    mma16816(acc[mi][2 * p],     a[mi], &b[p][0]);
                    mma16816(acc[mi][2 * p + 1], a[mi], &b[p][2]);
                }
        }
    }

#pragma unroll
    for (int ni = 0; ni < 8; ni++) {
        const int c = wid * 64 + ni * 8 + 2 * t;
        const float2 b2 = *(const float2*)(bp + c);
#pragma unroll
        for (int mi = 0; mi < 4; mi++)
#pragma unroll
            for (int h = 0; h < 2; h++) {
                const int row = mi * 16 + g + h * 8;
                *(__half2*)(outp + (bm0 + row) * (size_t)ldOut + c) =
                    __floats2half2_rn(acc[mi][ni][2 * h] + b2.x,
                                      acc[mi][ni][2 * h + 1] + b2.y);
            }
    }
}

// ---------------------------------------------------------------------------
// Host orchestration (26 launches)
// ---------------------------------------------------------------------------
extern "C" void kernel_launch(void* const* d_in, const int* in_sizes, int n_in,
                              void* d_out, int out_size)
{
    const float* qwen   = (const float*)d_in[0];
    const float* obs    = (const float*)d_in[1];
    const float* proj_W = (const float*)d_in[2];
    const float* proj_b = (const float*)d_in[3];
    const float* fuse_W = (const float*)d_in[4];
    const float* fuse_b = (const float*)d_in[5];
    const float* up_W   = (const float*)d_in[6];
    const float* up_b   = (const float*)d_in[7];
    const float* lat_W  = (const float*)d_in[8];
    const float* lat_b  = (const float*)d_in[9];
    const float* plog   = (const float*)d_in[10];
    const float* ln_g   = (const float*)d_in[11];
    const float* ln_b   = (const float*)d_in[12];
    const float* down_W = (const float*)d_in[13];
    const float* down_b = (const float*)d_in[14];
    const float* out1_W = (const float*)d_in[15];
    const float* out1_b = (const float*)d_in[16];
    const float* out2_W = (const float*)d_in[17];
    const float* out2_b = (const float*)d_in[18];
    float* out = (float*)d_out;

    __half *wh, *cat, *x0, *acts, *hbuf;
    cudaGetSymbolAddress((void**)&wh,    g_wh);
    cudaGetSymbolAddress((void**)&cat,   g_cat);
    cudaGetSymbolAddress((void**)&x0,    g_x0);
    cudaGetSymbolAddress((void**)&acts,  g_acts);
    cudaGetSymbolAddress((void**)&hbuf,  g_h);

    cudaFuncSetAttribute(k512<M_UPD_P>,  cudaFuncAttributeMaxDynamicSharedMemorySize, SMEM_K);
    cudaFuncSetAttribute(k512<M_UPD_NP>, cudaFuncAttributeMaxDynamicSharedMemorySize, SMEM_K);
    cudaFuncSetAttribute(k512<M_GELU>,   cudaFuncAttributeMaxDynamicSharedMemorySize, SMEM_K);
    cudaFuncSetAttribute(k512<M_ADD>,    cudaFuncAttributeMaxDynamicSharedMemorySize, SMEM_K);
    cudaFuncSetAttribute(kfuse0,         cudaFuncAttributeMaxDynamicSharedMemorySize, SMEM_K);
    cudaFuncSetAttribute(gemm_big<0>,    cudaFuncAttributeMaxDynamicSharedMemorySize, SMEM_BIG);
    cudaFuncSetAttribute(gemm_big<1>,    cudaFuncAttributeMaxDynamicSharedMemorySize, SMEM_BIG);

    const dim3 blk(256);

    // 1) weight converts
    wconv<<<1024, blk>>>((const float2*)proj_W, (const float2*)fuse_W,
                         (const float2*)up_W,   (const float2*)lat_W,
                         (const float2*)down_W, (const float2*)out1_W,
                         (const float2*)out2_W, (__half2*)wh);

    // 2) input projections + fuse (proven gemm_big)
    gemm_big<1><<<dim3(TOK / 64, 1, 4), blk, SMEM_BIG>>>(
        obs, wh + W_PROJ, proj_b, cat, DM);
    gemm_big<0><<<dim3(TOK / 64, 1, 1), blk, SMEM_BIG>>>(
        cat, wh + W_FUSE, fuse_b, x0, DC);

    // 3) init sweep (fused, verified)
    kfuse0<<<TOK / 64, blk, SMEM_K>>>(x0, acts, wh, up_b, ln_g, ln_b);

    // 4) settle
    for (int s = 0; s < 5; s++) {
        k512<M_UPD_P><<<TOK / 64, blk, SMEM_K>>>(
            acts + 1 * ASZ, x0, acts + 0 * ASZ,
            wh + W_DOWN + 1 * WSZ, wh + W_UP + 0 * WSZ, wh + W_LAT + 0 * WSZ,
            down_b + 1 * DC, up_b + 0 * DC, lat_b + 0 * DC,
            ln_g + 0 * DC, ln_b + 0 * DC, plog + 0 * DC,
            nullptr, acts + 0 * ASZ, DC);
        k512<M_UPD_P><<<TOK / 64, blk, SMEM_K>>>(
            acts + 2 * ASZ, acts + 0 * ASZ, acts + 1 * ASZ,
            wh + W_DOWN + 2 * WSZ, wh + W_UP + 1 * WSZ, wh + W_LAT + 1 * WSZ,
            down_b + 2 * DC, up_b + 1 * DC, lat_b + 1 * DC,
            ln_g + 1 * DC, ln_b + 1 * DC, plog + 1 * DC,
            nullptr, acts + 1 * ASZ, DC);
        k512<M_UPD_NP><<<TOK / 64, blk, SMEM_K>>>(
            nullptr, acts + 1 * ASZ, acts + 2 * ASZ,
            nullptr, wh + W_UP + 2 * WSZ, wh + W_LAT + 2 * WSZ,
            nullptr, up_b + 2 * DC, lat_b + 2 * DC,
            ln_g + 2 * DC, ln_b + 2 * DC, plog + 2 * DC,
            nullptr, acts + 2 * ASZ, DC);
        k512<M_UPD_NP><<<TOK / 64, blk, SMEM_K>>>(
            nullptr, acts + 2 * ASZ, acts + 3 * ASZ,
            nullptr, wh + W_UP + 3 * WSZ, wh + W_LAT + 3 * WSZ,
            nullptr, up_b + 3 * DC, lat_b + 3 * DC,
            ln_g + 3 * DC, ln_b + 3 * DC, plog + 3 * DC,
            nullptr, acts + 3 * ASZ, DC);
    }

    // 5) head
    k512<M_GELU><<<TOK / 64, blk, SMEM_K>>>(
        nullptr, acts + 3 * ASZ, nullptr,
        nullptr, wh + W_OUT1, nullptr,
        nullptr, out1_b, nullptr,
        nullptr, nullptr, nullptr,
        nullptr, hbuf, DC);
    k512<M_ADD><<<dim3(TOK / 64, 4), blk, SMEM_K>>>(
        nullptr, hbuf, nullptr,
        nullptr, wh + W_OUT2, nullptr,
        nullptr, out2_b, nullptr,
        nullptr, nullptr, nullptr,
        qwen, out, DM);
    (void)in_sizes; (void)n_in; (void)out_size;
}